// round 1
// baseline (speedup 1.0000x reference)
#include <cuda_runtime.h>
#include <cuda_fp16.h>

#define BB 64
#define CC 64
#define TT 2048
#define HH 128
#define GG 512   // 4H
#define H2 256   // 2H

// Scratch (device globals — no runtime allocation allowed)
__device__ __half g_zin[2][BB][TT][GG];   // 256 MiB: input projections (bias folded)
__device__ __half g_y[BB][TT][H2];        // 64 MiB: [h_fwd | h_bwd]
__device__ float  g_scores[BB][TT];       // attention logits

// ---------------- helpers ----------------
__device__ __forceinline__ float fast_ex2(float x) {
    float y; asm("ex2.approx.f32 %0, %1;" : "=f"(y) : "f"(x)); return y;
}
__device__ __forceinline__ float fast_rcp(float x) {
    float y; asm("rcp.approx.f32 %0, %1;" : "=f"(y) : "f"(x)); return y;
}
#define LOG2E 1.4426950408889634f
__device__ __forceinline__ float sigm(float x) {
    // 1/(1+e^-x); safe for all x (rcp(inf)=0)
    return fast_rcp(1.f + fast_ex2(-LOG2E * x));
}
__device__ __forceinline__ float tanha(float x) {
    // 1 - 2/(1+e^{2x}); safe for all x
    return 1.f - 2.f * fast_rcp(1.f + fast_ex2(2.f * LOG2E * x));
}
__device__ __forceinline__ float hsum(__half2 a) {
    return __low2float(a) + __high2float(a);
}
__device__ __forceinline__ __half2 u2h(unsigned u) {
    return *reinterpret_cast<__half2*>(&u);
}

// ---------------- K1: input projection  z = Wih @ x_t + (bih+bhh) ----------------
// grid (T/64, B), block 512 (one thread per gate row g)
__global__ void __launch_bounds__(512) k1_inproj(
    const float* __restrict__ x, const float* __restrict__ Wih,
    const float* __restrict__ bih, const float* __restrict__ bhh, int dir)
{
    __shared__ __align__(16) __half xs[64][72];  // [t][c], padded row (144B, 16B-aligned)
    const int tid = threadIdx.x;
    const int t0 = blockIdx.x * 64;
    const int b  = blockIdx.y;

    // stage x tile (coalesced over t)
    #pragma unroll
    for (int r = 0; r < 8; r++) {
        int idx = r * 512 + tid;
        int c = idx >> 6, tt = idx & 63;
        xs[tt][c] = __float2half(x[((size_t)b * CC + c) * TT + t0 + tt]);
    }

    // per-thread weight row (64 fp16 in registers)
    __half2 wv[32];
    const float4* wp = reinterpret_cast<const float4*>(Wih + tid * 64);
    #pragma unroll
    for (int k = 0; k < 16; k++) {
        float4 f = __ldg(wp + k);
        wv[2*k+0] = __floats2half2_rn(f.x, f.y);
        wv[2*k+1] = __floats2half2_rn(f.z, f.w);
    }
    const float bias = __ldg(bih + tid) + __ldg(bhh + tid);
    __syncthreads();

    __half* zrow = &g_zin[dir][b][t0][0];
    for (int tt = 0; tt < 64; tt++) {
        const uint4* xr = reinterpret_cast<const uint4*>(&xs[tt][0]);  // broadcast
        __half2 a0 = __float2half2_rn(0.f), a1 = a0, a2 = a0, a3 = a0;
        #pragma unroll
        for (int q = 0; q < 8; q++) {
            uint4 v = xr[q];
            a0 = __hfma2(wv[4*q+0], u2h(v.x), a0);
            a1 = __hfma2(wv[4*q+1], u2h(v.y), a1);
            a2 = __hfma2(wv[4*q+2], u2h(v.z), a2);
            a3 = __hfma2(wv[4*q+3], u2h(v.w), a3);
        }
        float s = hsum(a0) + hsum(a1) + hsum(a2) + hsum(a3);
        zrow[(size_t)tt * GG + tid] = __float2half(s + bias);
    }
}

// ---------------- K2: recurrence (one CTA per (b,dir)) ----------------
// 512 threads; thread owns gate row r; Whh row in 64 half2 registers.
__global__ void __launch_bounds__(512) k2_lstm(
    const float* __restrict__ Whh_f, const float* __restrict__ Whh_b)
{
    const int b = blockIdx.x, dir = blockIdx.y, tid = threadIdx.x;
    const float* Whh = dir ? Whh_b : Whh_f;

    __shared__ __align__(16) __half hs[HH];
    __shared__ float act[GG];

    __half2 w[64];
    const float4* wp = reinterpret_cast<const float4*>(Whh + tid * HH);
    #pragma unroll
    for (int k = 0; k < 32; k++) {
        float4 f = __ldg(wp + k);
        w[2*k+0] = __floats2half2_rn(f.x, f.y);
        w[2*k+1] = __floats2half2_rn(f.z, f.w);
    }
    if (tid < HH) hs[tid] = __float2half(0.f);
    float cst = 0.f;
    __syncthreads();

    const __half* zb = &g_zin[dir][b][0][0];
    int tt = dir ? (TT - 1) : 0;
    const int tstep = dir ? -1 : 1;
    float znext = __half2float(__ldg(zb + (size_t)tt * GG + tid));

    for (int step = 0; step < TT; step++) {
        float zc = znext;
        int ttn = tt + tstep;
        if (step < TT - 1)
            znext = __half2float(__ldg(zb + (size_t)ttn * GG + tid));  // prefetch next step

        const uint4* hr = reinterpret_cast<const uint4*>(hs);  // broadcast reads
        __half2 a0 = __float2half2_rn(0.f), a1 = a0, a2 = a0, a3 = a0;
        #pragma unroll
        for (int q = 0; q < 16; q++) {
            uint4 v = hr[q];
            a0 = __hfma2(w[4*q+0], u2h(v.x), a0);
            a1 = __hfma2(w[4*q+1], u2h(v.y), a1);
            a2 = __hfma2(w[4*q+2], u2h(v.z), a2);
            a3 = __hfma2(w[4*q+3], u2h(v.w), a3);
        }
        float a = zc + hsum(a0) + hsum(a1) + hsum(a2) + hsum(a3);
        act[tid] = a;
        __syncthreads();

        if (tid < HH) {
            float ig = act[tid], fg = act[tid + 128], gg = act[tid + 256], og = act[tid + 384];
            cst = sigm(fg) * cst + sigm(ig) * tanha(gg);
            float hv = sigm(og) * tanha(cst);
            hs[tid] = __float2half(hv);
            g_y[b][tt][dir * HH + tid] = __float2half(hv);
        }
        __syncthreads();
        tt = ttn;
    }
}

// ---------------- K3: attention logits  score = Wu . tanh(Wa @ y + ba) ----------------
// grid (T/64, B), block 256 (one thread per Wa row)
__global__ void __launch_bounds__(256) k3_attn(
    const float* __restrict__ Wa, const float* __restrict__ ba,
    const float* __restrict__ Wu)
{
    __shared__ __align__(16) __half ys[64 * H2];  // 32 KB tile
    __shared__ float sred[4][256];
    const int tid = threadIdx.x;
    const int t0 = blockIdx.x * 64, b = blockIdx.y;

    const uint4* gy = reinterpret_cast<const uint4*>(&g_y[b][t0][0]);
    uint4* ys4 = reinterpret_cast<uint4*>(ys);
    #pragma unroll
    for (int r = 0; r < 8; r++) ys4[r * 256 + tid] = gy[r * 256 + tid];

    __half2 w[128];
    const float4* wp = reinterpret_cast<const float4*>(Wa + tid * H2);
    #pragma unroll
    for (int k = 0; k < 64; k++) {
        float4 f = __ldg(wp + k);
        w[2*k+0] = __floats2half2_rn(f.x, f.y);
        w[2*k+1] = __floats2half2_rn(f.z, f.w);
    }
    const float bav = __ldg(ba + tid);
    const float wu  = __ldg(Wu + tid);
    __syncthreads();

    for (int pass = 0; pass < 16; pass++) {
        float part[4];
        #pragma unroll
        for (int it = 0; it < 4; it++) {
            const uint4* yr = reinterpret_cast<const uint4*>(&ys[(pass * 4 + it) * H2]);
            __half2 a0 = __float2half2_rn(0.f), a1 = a0;
            #pragma unroll
            for (int q = 0; q < 32; q++) {
                uint4 v = yr[q];
                a0 = __hfma2(w[4*q+0], u2h(v.x), a0);
                a1 = __hfma2(w[4*q+1], u2h(v.y), a1);
                a0 = __hfma2(w[4*q+2], u2h(v.z), a0);
                a1 = __hfma2(w[4*q+3], u2h(v.w), a1);
            }
            float u = tanha(hsum(a0) + hsum(a1) + bav);
            part[it] = u * wu;  // bu omitted: softmax shift-invariant
        }
        #pragma unroll
        for (int it = 0; it < 4; it++) sred[it][tid] = part[it];
        __syncthreads();

        int wid = tid >> 5, lane = tid & 31;
        if (wid < 4) {
            float v = 0.f;
            #pragma unroll
            for (int k = 0; k < 8; k++) v += sred[wid][lane + 32 * k];
            #pragma unroll
            for (int off = 16; off > 0; off >>= 1)
                v += __shfl_down_sync(0xffffffffu, v, off);
            if (lane == 0) g_scores[b][t0 + pass * 4 + wid] = v;
        }
        __syncthreads();
    }
}

// ---------------- K4: softmax over T + weighted sum ----------------
// grid B, block 256 (one thread per output channel)
__global__ void __launch_bounds__(256) k4_soft(float* __restrict__ out)
{
    __shared__ float wb[TT];     // 8 KB softmax weights
    __shared__ float red[256];
    const int b = blockIdx.x, tid = threadIdx.x;

    float m = -1e30f;
    #pragma unroll
    for (int r = 0; r < 8; r++) m = fmaxf(m, g_scores[b][r * 256 + tid]);
    red[tid] = m; __syncthreads();
    for (int off = 128; off > 0; off >>= 1) {
        if (tid < off) red[tid] = fmaxf(red[tid], red[tid + off]);
        __syncthreads();
    }
    const float mx = red[0];
    __syncthreads();

    float ls = 0.f;
    #pragma unroll
    for (int r = 0; r < 8; r++) {
        int t = r * 256 + tid;
        float e = fast_ex2((g_scores[b][t] - mx) * LOG2E);
        wb[t] = e; ls += e;
    }
    red[tid] = ls; __syncthreads();
    for (int off = 128; off > 0; off >>= 1) {
        if (tid < off) red[tid] += red[tid + off];
        __syncthreads();
    }
    const float rz = __frcp_rn(red[0]);

    float acc = 0.f;
    const __half* yp = &g_y[b][0][tid];
    for (int t = 0; t < TT; t += 8) {
        #pragma unroll
        for (int u = 0; u < 8; u++)
            acc += wb[t + u] * __half2float(__ldg(yp + (size_t)(t + u) * H2));
    }
    out[b * H2 + tid] = acc * rz;
}

// ---------------- launch ----------------
extern "C" void kernel_launch(void* const* d_in, const int* in_sizes, int n_in,
                              void* d_out, int out_size)
{
    const float* x     = (const float*)d_in[0];
    const float* Wih_f = (const float*)d_in[1];
    const float* Whh_f = (const float*)d_in[2];
    const float* bih_f = (const float*)d_in[3];
    const float* bhh_f = (const float*)d_in[4];
    const float* Wih_b = (const float*)d_in[5];
    const float* Whh_b = (const float*)d_in[6];
    const float* bih_b = (const float*)d_in[7];
    const float* bhh_b = (const float*)d_in[8];
    const float* Wa    = (const float*)d_in[9];
    const float* ba    = (const float*)d_in[10];
    const float* Wu    = (const float*)d_in[11];
    // d_in[12] (bu) unused: softmax is shift-invariant
    float* out = (float*)d_out;

    k1_inproj<<<dim3(TT / 64, BB), 512>>>(x, Wih_f, bih_f, bhh_f, 0);
    k1_inproj<<<dim3(TT / 64, BB), 512>>>(x, Wih_b, bih_b, bhh_b, 1);
    k2_lstm<<<dim3(BB, 2), 512>>>(Whh_f, Whh_b);
    k3_attn<<<dim3(TT / 64, BB), 256>>>(Wa, ba, Wu);
    k4_soft<<<BB, 256>>>(out);
}

// round 3
// speedup vs baseline: 1.1900x; 1.1900x over previous
#include <cuda_runtime.h>
#include <cuda_fp16.h>
#include <cstdint>

#define BB 64
#define CC 64
#define TT 2048
#define HH 128
#define GG 512   // 4H
#define H2 256   // 2H

// Scratch (device globals — no runtime allocation allowed)
__device__ __half g_zin[2][BB][TT][GG];     // 256 MiB input projections (bias folded)
__device__ __half g_y[BB][TT][H2];          // 64 MiB [h_fwd | h_bwd]
__device__ float  g_scores[BB][TT];         // attention logits
__device__ __align__(16) __half g_Wa_h[H2 * H2];    // Wa fp16, row-major [g][k]
__device__ __align__(16) __half g_W1h[1024 * CC];   // [Wih_f; Wih_b] fp16 row-major
__device__ float  g_b1[1024];               // bih+bhh per dir, concatenated

// ---------------- helpers ----------------
__device__ __forceinline__ float fast_ex2(float x) {
    float y; asm("ex2.approx.f32 %0, %1;" : "=f"(y) : "f"(x)); return y;
}
__device__ __forceinline__ float fast_rcp(float x) {
    float y; asm("rcp.approx.f32 %0, %1;" : "=f"(y) : "f"(x)); return y;
}
#define LOG2E 1.4426950408889634f
__device__ __forceinline__ float sigm(float x) {
    return fast_rcp(1.f + fast_ex2(-LOG2E * x));
}
__device__ __forceinline__ float tanha(float x) {
    return 1.f - 2.f * fast_rcp(1.f + fast_ex2(2.f * LOG2E * x));
}
__device__ __forceinline__ float hsum(__half2 a) {
    return __low2float(a) + __high2float(a);
}
__device__ __forceinline__ __half2 u2h(unsigned u) {
    return *reinterpret_cast<__half2*>(&u);
}

// m16n8k16 row.col f16 -> f32 (base-target PTX, lowers to HMMA on sm_103)
__device__ __forceinline__ void mma16816(float* d, const uint32_t* a,
                                         uint32_t b0, uint32_t b1, const float* c) {
    asm volatile(
        "mma.sync.aligned.m16n8k16.row.col.f32.f16.f16.f32 "
        "{%0,%1,%2,%3}, {%4,%5,%6,%7}, {%8,%9}, {%10,%11,%12,%13};"
        : "=f"(d[0]), "=f"(d[1]), "=f"(d[2]), "=f"(d[3])
        : "r"(a[0]), "r"(a[1]), "r"(a[2]), "r"(a[3]),
          "r"(b0), "r"(b1),
          "f"(c[0]), "f"(c[1]), "f"(c[2]), "f"(c[3]));
}

// ---------------- prep kernels (run once per launch; tiny) ----------------
__global__ void __launch_bounds__(256) p_wa(const float* __restrict__ Wa) {
    int i = blockIdx.x * 256 + threadIdx.x;           // 65536
    g_Wa_h[i] = __float2half(__ldg(Wa + i));
}
__global__ void __launch_bounds__(256) p_w1(
    const float* __restrict__ Wf, const float* __restrict__ Wb,
    const float* __restrict__ bif, const float* __restrict__ bhf,
    const float* __restrict__ bib, const float* __restrict__ bhb)
{
    int i = blockIdx.x * 256 + threadIdx.x;           // 65536
    g_W1h[i] = __float2half(i < 32768 ? __ldg(Wf + i) : __ldg(Wb + i - 32768));
    if (i < 512)       g_b1[i] = __ldg(bif + i) + __ldg(bhf + i);
    else if (i < 1024) g_b1[i] = __ldg(bib + i - 512) + __ldg(bhb + i - 512);
}

// ---------------- K1: z[t][1024g] = x_tile @ W1^T + bias, via mma.sync ----------------
// grid (T/128, B), 256 threads. smem: W1 fp16 padded + x tile fp16 padded + bias.
#define K1_WS   0                        // 1024 rows x 72 halfs = 147456 B
#define K1_XS   147456                   // 128 rows x 66 halfs  = 16896 B
#define K1_BS   164352                   // 1024 floats          = 4096 B
#define K1_TOT  168448

__global__ void __launch_bounds__(256) k1_mma(const float* __restrict__ x)
{
    extern __shared__ __align__(16) char smem[];
    const int tid = threadIdx.x;
    const int t0 = blockIdx.x * 128;
    const int b  = blockIdx.y;

    // W1 [1024][64] fp16 -> smem rows padded to 72 halfs (144B, conflict-free)
    {
        const uint4* src = reinterpret_cast<const uint4*>(g_W1h);
        #pragma unroll
        for (int i = 0; i < 32; i++) {
            int idx = i * 256 + tid;                 // 0..8191 uint4
            int r = idx >> 3, c = idx & 7;
            *reinterpret_cast<uint4*>(smem + K1_WS + r * 144 + c * 16) = __ldg(src + idx);
        }
    }
    // x tile: [c][t] fp32 -> smem [t][c] fp16, rows padded to 66 halfs
    #pragma unroll
    for (int i = 0; i < 32; i++) {
        int idx = i * 256 + tid;                     // 0..8191
        int c = idx >> 7, tl = idx & 127;
        float v = __ldg(x + ((size_t)b * CC + c) * TT + t0 + tl);
        *reinterpret_cast<__half*>(smem + K1_XS + tl * 132 + c * 2) = __float2half(v);
    }
    // bias
    #pragma unroll
    for (int i = 0; i < 4; i++) {
        int g = i * 256 + tid;
        *reinterpret_cast<float*>(smem + K1_BS + g * 4) = g_b1[g];
    }
    __syncthreads();

    const int w = tid >> 5, lane = tid & 31;
    const int qr = lane >> 2, q4 = lane & 3;
    const int m0 = w * 16;

    // A fragments: rows m0+qr (+8), k = q4*2 + {0,1} per 16-k tile (4 tiles)
    uint32_t afr[4][4];
    {
        const char* xb = smem + K1_XS;
        #pragma unroll
        for (int kt = 0; kt < 4; kt++) {
            int kb = q4 * 2 + kt * 16;
            afr[kt][0] = *reinterpret_cast<const uint32_t*>(xb + (m0 + qr) * 132 + kb * 2);
            afr[kt][1] = *reinterpret_cast<const uint32_t*>(xb + (m0 + qr + 8) * 132 + kb * 2);
            afr[kt][2] = *reinterpret_cast<const uint32_t*>(xb + (m0 + qr) * 132 + (kb + 8) * 2);
            afr[kt][3] = *reinterpret_cast<const uint32_t*>(xb + (m0 + qr + 8) * 132 + (kb + 8) * 2);
        }
    }

    const char* wsb = smem + K1_WS;
    const int t_ = t0 + m0 + qr;
    #pragma unroll 4
    for (int j = 0; j < 128; j++) {                  // n-tiles over 1024 gate rows
        float acc[4] = {0.f, 0.f, 0.f, 0.f};
        int nr = j * 8 + qr;                         // B row (gate index)
        #pragma unroll
        for (int kt = 0; kt < 4; kt++) {
            int kb = q4 * 2 + kt * 16;
            uint32_t b0 = *reinterpret_cast<const uint32_t*>(wsb + nr * 144 + kb * 2);
            uint32_t b1 = *reinterpret_cast<const uint32_t*>(wsb + nr * 144 + (kb + 8) * 2);
            mma16816(acc, afr[kt], b0, b1, acc);
        }
        int gcol = j * 8 + q4 * 2;
        float2 bs = *reinterpret_cast<const float2*>(smem + K1_BS + gcol * 4);
        int dir = gcol >> 9, g = gcol & 511;
        __half2 v01 = __floats2half2_rn(acc[0] + bs.x, acc[1] + bs.y);
        __half2 v23 = __floats2half2_rn(acc[2] + bs.x, acc[3] + bs.y);
        *reinterpret_cast<__half2*>(&g_zin[dir][b][t_][g]) = v01;
        *reinterpret_cast<__half2*>(&g_zin[dir][b][t_ + 8][g]) = v23;
    }
}

// ---------------- K2: recurrence (one CTA per (b,dir)) ----------------
__global__ void __launch_bounds__(512) k2_lstm(
    const float* __restrict__ Whh_f, const float* __restrict__ Whh_b)
{
    const int b = blockIdx.x, dir = blockIdx.y, tid = threadIdx.x;
    const float* Whh = dir ? Whh_b : Whh_f;

    __shared__ __align__(16) __half hs[HH];
    __shared__ float act[GG];

    __half2 w[64];
    const float4* wp = reinterpret_cast<const float4*>(Whh + tid * HH);
    #pragma unroll
    for (int k = 0; k < 32; k++) {
        float4 f = __ldg(wp + k);
        w[2*k+0] = __floats2half2_rn(f.x, f.y);
        w[2*k+1] = __floats2half2_rn(f.z, f.w);
    }
    if (tid < HH) hs[tid] = __float2half(0.f);
    float cst = 0.f;
    __syncthreads();

    const __half* zb = &g_zin[dir][b][0][0];
    int tt = dir ? (TT - 1) : 0;
    const int tstep = dir ? -1 : 1;
    const int grp = tid >> 7;   // 0:i 1:f 2:g 3:o
    __half* ydst = &g_y[b][0][dir * HH + tid];

    float z0 = __half2float(__ldg(zb + (size_t)tt * GG + tid));
    float z1 = __half2float(__ldg(zb + (size_t)(tt + tstep) * GG + tid));

    for (int step = 0; step < TT; step++) {
        float zc = z0;
        z0 = z1;
        if (step + 2 < TT)
            z1 = __half2float(__ldg(zb + (size_t)(tt + 2 * tstep) * GG + tid));

        const uint4* hr = reinterpret_cast<const uint4*>(hs);
        __half2 a0 = __float2half2_rn(0.f), a1 = a0, a2 = a0, a3 = a0;
        #pragma unroll
        for (int q = 0; q < 16; q++) {
            uint4 v = hr[q];
            a0 = __hfma2(w[4*q+0], u2h(v.x), a0);
            a1 = __hfma2(w[4*q+1], u2h(v.y), a1);
            a2 = __hfma2(w[4*q+2], u2h(v.z), a2);
            a3 = __hfma2(w[4*q+3], u2h(v.w), a3);
        }
        float a = zc + hsum(a0) + hsum(a1) + hsum(a2) + hsum(a3);
        act[tid] = (grp == 2) ? tanha(a) : sigm(a);
        __syncthreads();

        if (tid < HH) {
            float iv = act[tid], fv = act[tid + 128];
            float gv = act[tid + 256], ov = act[tid + 384];
            cst = fv * cst + iv * gv;
            float hv = ov * tanha(cst);
            __half hh = __float2half(hv);
            hs[tid] = hh;
            ydst[(size_t)tt * H2] = hh;
        }
        __syncthreads();
        tt += tstep;
    }
}

// ---------------- K3: attention logits via mma.sync ----------------
// grid (T/128, B), 256 threads. score[t] = sum_g tanh((y@Wa^T)[t][g] + ba[g]) * Wu[g]
#define K3_WA   0                        // 256 rows x 264 halfs = 135168 B
#define K3_YS   135168                   // 128 rows x 264 halfs = 67584 B
#define K3_BW   202752                   // 256 float2           = 2048 B
#define K3_TOT  204800

__global__ void __launch_bounds__(256) k3_mma(
    const float* __restrict__ ba, const float* __restrict__ Wu)
{
    extern __shared__ __align__(16) char smem[];
    const int tid = threadIdx.x;
    const int t0 = blockIdx.x * 128;
    const int b  = blockIdx.y;

    // Wa fp16 [256][256] -> smem rows padded to 264 halfs (528B)
    {
        const uint4* src = reinterpret_cast<const uint4*>(g_Wa_h);
        #pragma unroll
        for (int i = 0; i < 32; i++) {
            int idx = i * 256 + tid;                 // 0..8191 uint4
            int r = idx >> 5, c = idx & 31;
            *reinterpret_cast<uint4*>(smem + K3_WA + r * 528 + c * 16) = __ldg(src + idx);
        }
    }
    // y tile [128][256] fp16 -> smem padded
    {
        const uint4* src = reinterpret_cast<const uint4*>(&g_y[b][t0][0]);
        #pragma unroll
        for (int i = 0; i < 16; i++) {
            int idx = i * 256 + tid;                 // 0..4095 uint4
            int r = idx >> 5, c = idx & 31;
            *reinterpret_cast<uint4*>(smem + K3_YS + r * 528 + c * 16) = src[idx];
        }
    }
    *reinterpret_cast<float2*>(smem + K3_BW + tid * 8) =
        make_float2(__ldg(ba + tid), __ldg(Wu + tid));
    __syncthreads();

    const int w = tid >> 5, lane = tid & 31;
    const int qr = lane >> 2, q4 = lane & 3;
    const int m0 = w * 16;

    // A fragments: 16 k-tiles (K=256)
    uint32_t afr[16][4];
    {
        const char* yb = smem + K3_YS;
        #pragma unroll
        for (int kt = 0; kt < 16; kt++) {
            int kb = q4 * 2 + kt * 16;
            afr[kt][0] = *reinterpret_cast<const uint32_t*>(yb + (m0 + qr) * 528 + kb * 2);
            afr[kt][1] = *reinterpret_cast<const uint32_t*>(yb + (m0 + qr + 8) * 528 + kb * 2);
            afr[kt][2] = *reinterpret_cast<const uint32_t*>(yb + (m0 + qr) * 528 + (kb + 8) * 2);
            afr[kt][3] = *reinterpret_cast<const uint32_t*>(yb + (m0 + qr + 8) * 528 + (kb + 8) * 2);
        }
    }

    const char* wab = smem + K3_WA;
    const float2* bw = reinterpret_cast<const float2*>(smem + K3_BW);
    float s0 = 0.f, s1 = 0.f;

    #pragma unroll 2
    for (int j = 0; j < 32; j++) {                   // n-tiles over 256 gates
        float acc[4] = {0.f, 0.f, 0.f, 0.f};
        int nr = j * 8 + qr;
        #pragma unroll
        for (int kt = 0; kt < 16; kt++) {
            int kb = q4 * 2 + kt * 16;
            uint32_t b0 = *reinterpret_cast<const uint32_t*>(wab + nr * 528 + kb * 2);
            uint32_t b1 = *reinterpret_cast<const uint32_t*>(wab + nr * 528 + (kb + 8) * 2);
            mma16816(acc, afr[kt], b0, b1, acc);
        }
        int n0 = j * 8 + q4 * 2;
        float2 p0 = bw[n0], p1 = bw[n0 + 1];
        s0 += tanha(acc[0] + p0.x) * p0.y + tanha(acc[1] + p1.x) * p1.y;
        s1 += tanha(acc[2] + p0.x) * p0.y + tanha(acc[3] + p1.x) * p1.y;
    }
    // reduce across the quad (lanes sharing a row)
    s0 += __shfl_xor_sync(0xffffffffu, s0, 1);
    s0 += __shfl_xor_sync(0xffffffffu, s0, 2);
    s1 += __shfl_xor_sync(0xffffffffu, s1, 1);
    s1 += __shfl_xor_sync(0xffffffffu, s1, 2);
    if (q4 == 0) {
        g_scores[b][t0 + m0 + qr]     = s0;
        g_scores[b][t0 + m0 + qr + 8] = s1;
    }
}

// ---------------- K4: softmax over T + weighted sum ----------------
__global__ void __launch_bounds__(256) k4_soft(float* __restrict__ out)
{
    __shared__ float wb[TT];
    __shared__ float red[256];
    const int b = blockIdx.x, tid = threadIdx.x;

    float m = -1e30f;
    #pragma unroll
    for (int r = 0; r < 8; r++) m = fmaxf(m, g_scores[b][r * 256 + tid]);
    red[tid] = m; __syncthreads();
    for (int off = 128; off > 0; off >>= 1) {
        if (tid < off) red[tid] = fmaxf(red[tid], red[tid + off]);
        __syncthreads();
    }
    const float mx = red[0];
    __syncthreads();

    float ls = 0.f;
    #pragma unroll
    for (int r = 0; r < 8; r++) {
        int t = r * 256 + tid;
        float e = fast_ex2((g_scores[b][t] - mx) * LOG2E);
        wb[t] = e; ls += e;
    }
    red[tid] = ls; __syncthreads();
    for (int off = 128; off > 0; off >>= 1) {
        if (tid < off) red[tid] += red[tid + off];
        __syncthreads();
    }
    const float rz = __frcp_rn(red[0]);

    float acc = 0.f;
    const __half* yp = &g_y[b][0][tid];
    for (int t = 0; t < TT; t += 8) {
        #pragma unroll
        for (int u = 0; u < 8; u++)
            acc += wb[t + u] * __half2float(__ldg(yp + (size_t)(t + u) * H2));
    }
    out[b * H2 + tid] = acc * rz;
}

// ---------------- launch ----------------
extern "C" void kernel_launch(void* const* d_in, const int* in_sizes, int n_in,
                              void* d_out, int out_size)
{
    const float* x     = (const float*)d_in[0];
    const float* Wih_f = (const float*)d_in[1];
    const float* Whh_f = (const float*)d_in[2];
    const float* bih_f = (const float*)d_in[3];
    const float* bhh_f = (const float*)d_in[4];
    const float* Wih_b = (const float*)d_in[5];
    const float* Whh_b = (const float*)d_in[6];
    const float* bih_b = (const float*)d_in[7];
    const float* bhh_b = (const float*)d_in[8];
    const float* Wa    = (const float*)d_in[9];
    const float* ba    = (const float*)d_in[10];
    const float* Wu    = (const float*)d_in[11];
    float* out = (float*)d_out;

    cudaFuncSetAttribute(k1_mma, cudaFuncAttributeMaxDynamicSharedMemorySize, K1_TOT);
    cudaFuncSetAttribute(k3_mma, cudaFuncAttributeMaxDynamicSharedMemorySize, K3_TOT);

    p_wa<<<256, 256>>>(Wa);
    p_w1<<<256, 256>>>(Wih_f, Wih_b, bih_f, bhh_f, bih_b, bhh_b);
    k1_mma<<<dim3(TT / 128, BB), 256, K1_TOT>>>(x);
    k2_lstm<<<dim3(BB, 2), 512>>>(Whh_f, Whh_b);
    k3_mma<<<dim3(TT / 128, BB), 256, K3_TOT>>>(ba, Wu);
    k4_soft<<<BB, 256>>>(out);
}

// round 4
// speedup vs baseline: 1.2208x; 1.0258x over previous
#include <cuda_runtime.h>
#include <cuda_fp16.h>
#include <cstdint>

#define BB 64
#define CC 64
#define TT 2048
#define HH 128
#define GG 512   // 4H
#define H2 256   // 2H

// Scratch (device globals — no runtime allocation allowed)
__device__ __half g_zin[2][BB][TT][GG];     // 256 MiB input projections (bias folded)
__device__ __half g_y[BB][TT][H2];          // 64 MiB [h_fwd | h_bwd]
__device__ float  g_scores[BB][TT];         // attention logits
__device__ __align__(16) __half g_Wa_h[H2 * H2];    // Wa fp16, row-major [g][k]
__device__ __align__(16) __half g_W1h[1024 * CC];   // [Wih_f; Wih_b] fp16 row-major
__device__ float  g_b1[1024];               // bih+bhh per dir, concatenated

// ---------------- helpers ----------------
__device__ __forceinline__ float fast_ex2(float x) {
    float y; asm("ex2.approx.f32 %0, %1;" : "=f"(y) : "f"(x)); return y;
}
__device__ __forceinline__ float fast_rcp(float x) {
    float y; asm("rcp.approx.f32 %0, %1;" : "=f"(y) : "f"(x)); return y;
}
#define LOG2E 1.4426950408889634f
__device__ __forceinline__ float sigm(float x) {
    return fast_rcp(1.f + fast_ex2(-LOG2E * x));
}
__device__ __forceinline__ float tanha(float x) {
    return 1.f - 2.f * fast_rcp(1.f + fast_ex2(2.f * LOG2E * x));
}
__device__ __forceinline__ float hsum(__half2 a) {
    return __low2float(a) + __high2float(a);
}
__device__ __forceinline__ __half2 u2h(unsigned u) {
    return *reinterpret_cast<__half2*>(&u);
}

// m16n8k16 row.col f16 -> f32 (base-target PTX, lowers to HMMA on sm_103)
__device__ __forceinline__ void mma16816(float* d, const uint32_t* a,
                                         uint32_t b0, uint32_t b1, const float* c) {
    asm volatile(
        "mma.sync.aligned.m16n8k16.row.col.f32.f16.f16.f32 "
        "{%0,%1,%2,%3}, {%4,%5,%6,%7}, {%8,%9}, {%10,%11,%12,%13};"
        : "=f"(d[0]), "=f"(d[1]), "=f"(d[2]), "=f"(d[3])
        : "r"(a[0]), "r"(a[1]), "r"(a[2]), "r"(a[3]),
          "r"(b0), "r"(b1),
          "f"(c[0]), "f"(c[1]), "f"(c[2]), "f"(c[3]));
}

// ---------------- prep kernels (tiny) ----------------
__global__ void __launch_bounds__(256) p_wa(const float* __restrict__ Wa) {
    int i = blockIdx.x * 256 + threadIdx.x;           // 65536
    g_Wa_h[i] = __float2half(__ldg(Wa + i));
}
__global__ void __launch_bounds__(256) p_w1(
    const float* __restrict__ Wf, const float* __restrict__ Wb,
    const float* __restrict__ bif, const float* __restrict__ bhf,
    const float* __restrict__ bib, const float* __restrict__ bhb)
{
    int i = blockIdx.x * 256 + threadIdx.x;           // 65536
    g_W1h[i] = __float2half(i < 32768 ? __ldg(Wf + i) : __ldg(Wb + i - 32768));
    if (i < 512)       g_b1[i] = __ldg(bif + i) + __ldg(bhf + i);
    else if (i < 1024) g_b1[i] = __ldg(bib + i - 512) + __ldg(bhb + i - 512);
}

// ---------------- K1: z[t][1024g] = x_tile @ W1^T + bias, via mma.sync ----------------
#define K1_WS   0                        // 1024 rows x 72 halfs = 147456 B
#define K1_XS   147456                   // 128 rows x 66 halfs  = 16896 B
#define K1_BS   164352                   // 1024 floats          = 4096 B
#define K1_TOT  168448

__global__ void __launch_bounds__(256) k1_mma(const float* __restrict__ x)
{
    extern __shared__ __align__(16) char smem[];
    const int tid = threadIdx.x;
    const int t0 = blockIdx.x * 128;
    const int b  = blockIdx.y;

    {
        const uint4* src = reinterpret_cast<const uint4*>(g_W1h);
        #pragma unroll
        for (int i = 0; i < 32; i++) {
            int idx = i * 256 + tid;
            int r = idx >> 3, c = idx & 7;
            *reinterpret_cast<uint4*>(smem + K1_WS + r * 144 + c * 16) = __ldg(src + idx);
        }
    }
    #pragma unroll
    for (int i = 0; i < 32; i++) {
        int idx = i * 256 + tid;
        int c = idx >> 7, tl = idx & 127;
        float v = __ldg(x + ((size_t)b * CC + c) * TT + t0 + tl);
        *reinterpret_cast<__half*>(smem + K1_XS + tl * 132 + c * 2) = __float2half(v);
    }
    #pragma unroll
    for (int i = 0; i < 4; i++) {
        int g = i * 256 + tid;
        *reinterpret_cast<float*>(smem + K1_BS + g * 4) = g_b1[g];
    }
    __syncthreads();

    const int w = tid >> 5, lane = tid & 31;
    const int qr = lane >> 2, q4 = lane & 3;
    const int m0 = w * 16;

    uint32_t afr[4][4];
    {
        const char* xb = smem + K1_XS;
        #pragma unroll
        for (int kt = 0; kt < 4; kt++) {
            int kb = q4 * 2 + kt * 16;
            afr[kt][0] = *reinterpret_cast<const uint32_t*>(xb + (m0 + qr) * 132 + kb * 2);
            afr[kt][1] = *reinterpret_cast<const uint32_t*>(xb + (m0 + qr + 8) * 132 + kb * 2);
            afr[kt][2] = *reinterpret_cast<const uint32_t*>(xb + (m0 + qr) * 132 + (kb + 8) * 2);
            afr[kt][3] = *reinterpret_cast<const uint32_t*>(xb + (m0 + qr + 8) * 132 + (kb + 8) * 2);
        }
    }

    const char* wsb = smem + K1_WS;
    const int t_ = t0 + m0 + qr;
    #pragma unroll 4
    for (int j = 0; j < 128; j++) {
        float acc[4] = {0.f, 0.f, 0.f, 0.f};
        int nr = j * 8 + qr;
        #pragma unroll
        for (int kt = 0; kt < 4; kt++) {
            int kb = q4 * 2 + kt * 16;
            uint32_t b0 = *reinterpret_cast<const uint32_t*>(wsb + nr * 144 + kb * 2);
            uint32_t b1 = *reinterpret_cast<const uint32_t*>(wsb + nr * 144 + (kb + 8) * 2);
            mma16816(acc, afr[kt], b0, b1, acc);
        }
        int gcol = j * 8 + q4 * 2;
        float2 bs = *reinterpret_cast<const float2*>(smem + K1_BS + gcol * 4);
        int dir = gcol >> 9, g = gcol & 511;
        __half2 v01 = __floats2half2_rn(acc[0] + bs.x, acc[1] + bs.y);
        __half2 v23 = __floats2half2_rn(acc[2] + bs.x, acc[3] + bs.y);
        *reinterpret_cast<__half2*>(&g_zin[dir][b][t_][g]) = v01;
        *reinterpret_cast<__half2*>(&g_zin[dir][b][t_ + 8][g]) = v23;
    }
}

// ---------------- K2: recurrence, 256 threads, shfl gate exchange, 1 barrier/step ----
// warp w lane L: element e = w*16 + (L&15). L<16 owns rows (i[e], f[e]);
// L>=16 owns (g[e], o[e]) and ships tanh(g), sigm(o) down via shfl.
__global__ void __launch_bounds__(256) k2_lstm(
    const float* __restrict__ Whh_f, const float* __restrict__ Whh_b)
{
    const int b = blockIdx.x, dir = blockIdx.y, tid = threadIdx.x;
    const float* Whh = dir ? Whh_b : Whh_f;

    __shared__ __align__(16) __half hs[HH];

    const int w = tid >> 5, lane = tid & 31;
    const int e  = w * 16 + (lane & 15);
    const int hi = lane >> 4;                 // 0: (i,f)  1: (g,o)
    const int row0 = e + hi * 256;
    const int row1 = row0 + 128;

    __half2 w0[64], w1[64];
    {
        const float4* p0 = reinterpret_cast<const float4*>(Whh + row0 * HH);
        const float4* p1 = reinterpret_cast<const float4*>(Whh + row1 * HH);
        #pragma unroll
        for (int k = 0; k < 32; k++) {
            float4 f = __ldg(p0 + k);
            w0[2*k]   = __floats2half2_rn(f.x, f.y);
            w0[2*k+1] = __floats2half2_rn(f.z, f.w);
            float4 g = __ldg(p1 + k);
            w1[2*k]   = __floats2half2_rn(g.x, g.y);
            w1[2*k+1] = __floats2half2_rn(g.z, g.w);
        }
    }
    if (tid < HH) hs[tid] = __float2half(0.f);
    float cst = 0.f;
    __syncthreads();

    const __half* zb = &g_zin[dir][b][0][0];
    int tt = dir ? (TT - 1) : 0;
    const int tstep = dir ? -1 : 1;
    __half* ydst = &g_y[b][0][dir * HH + e];

    // depth-2 z prefetch (2 rows per thread)
    float za0 = __half2float(__ldg(zb + (size_t)tt * GG + row0));
    float za1 = __half2float(__ldg(zb + (size_t)tt * GG + row1));
    float zb0 = __half2float(__ldg(zb + (size_t)(tt + tstep) * GG + row0));
    float zb1 = __half2float(__ldg(zb + (size_t)(tt + tstep) * GG + row1));

    for (int step = 0; step < TT; step++) {
        float zc0 = za0, zc1 = za1;
        za0 = zb0; za1 = zb1;
        if (step + 2 < TT) {
            const __half* zp = zb + (size_t)(tt + 2 * tstep) * GG;
            zb0 = __half2float(__ldg(zp + row0));
            zb1 = __half2float(__ldg(zp + row1));
        }

        const uint4* hr = reinterpret_cast<const uint4*>(hs);
        __half2 p0 = __float2half2_rn(0.f), p1 = p0, p2 = p0, p3 = p0;
        __half2 q0 = p0, q1 = p0, q2 = p0, q3 = p0;
        #pragma unroll
        for (int q = 0; q < 16; q++) {
            uint4 v = hr[q];
            p0 = __hfma2(w0[4*q+0], u2h(v.x), p0);
            q0 = __hfma2(w1[4*q+0], u2h(v.x), q0);
            p1 = __hfma2(w0[4*q+1], u2h(v.y), p1);
            q1 = __hfma2(w1[4*q+1], u2h(v.y), q1);
            p2 = __hfma2(w0[4*q+2], u2h(v.z), p2);
            q2 = __hfma2(w1[4*q+2], u2h(v.z), q2);
            p3 = __hfma2(w0[4*q+3], u2h(v.w), p3);
            q3 = __hfma2(w1[4*q+3], u2h(v.w), q3);
        }
        __half2 pA = __hadd2(p0, p1), pB = __hadd2(p2, p3);
        __half2 qA = __hadd2(q0, q1), qB = __hadd2(q2, q3);
        float s0 = zc0 + hsum(pA) + hsum(pB);
        float s1 = zc1 + hsum(qA) + hsum(qB);

        // lanes<16: n0=sigm(i), n1=sigm(f);  lanes>=16: n0=tanh(g), n1=sigm(o)
        float n0 = hi ? tanha(s0) : sigm(s0);
        float n1 = sigm(s1);
        float r0 = __shfl_down_sync(0xffffffffu, n0, 16);
        float r1 = __shfl_down_sync(0xffffffffu, n1, 16);

        if (hi == 0) {
            cst = n1 * cst + n0 * r0;          // c = σ(f)c + σ(i)tanh(g)
            float hv = r1 * tanha(cst);        // h = σ(o)tanh(c)
            __half hh = __float2half(hv);
            hs[e] = hh;
            ydst[(size_t)tt * H2] = hh;
        }
        __syncthreads();
        tt += tstep;
    }
}

// ---------------- K3: attention logits via mma.sync ----------------
#define K3_WA   0                        // 256 rows x 264 halfs = 135168 B
#define K3_YS   135168                   // 128 rows x 264 halfs = 67584 B
#define K3_BW   202752                   // 256 float2           = 2048 B
#define K3_TOT  204800

__global__ void __launch_bounds__(256) k3_mma(
    const float* __restrict__ ba, const float* __restrict__ Wu)
{
    extern __shared__ __align__(16) char smem[];
    const int tid = threadIdx.x;
    const int t0 = blockIdx.x * 128;
    const int b  = blockIdx.y;

    {
        const uint4* src = reinterpret_cast<const uint4*>(g_Wa_h);
        #pragma unroll
        for (int i = 0; i < 32; i++) {
            int idx = i * 256 + tid;
            int r = idx >> 5, c = idx & 31;
            *reinterpret_cast<uint4*>(smem + K3_WA + r * 528 + c * 16) = __ldg(src + idx);
        }
    }
    {
        const uint4* src = reinterpret_cast<const uint4*>(&g_y[b][t0][0]);
        #pragma unroll
        for (int i = 0; i < 16; i++) {
            int idx = i * 256 + tid;
            int r = idx >> 5, c = idx & 31;
            *reinterpret_cast<uint4*>(smem + K3_YS + r * 528 + c * 16) = src[idx];
        }
    }
    *reinterpret_cast<float2*>(smem + K3_BW + tid * 8) =
        make_float2(__ldg(ba + tid), __ldg(Wu + tid));
    __syncthreads();

    const int w = tid >> 5, lane = tid & 31;
    const int qr = lane >> 2, q4 = lane & 3;
    const int m0 = w * 16;

    uint32_t afr[16][4];
    {
        const char* yb = smem + K3_YS;
        #pragma unroll
        for (int kt = 0; kt < 16; kt++) {
            int kb = q4 * 2 + kt * 16;
            afr[kt][0] = *reinterpret_cast<const uint32_t*>(yb + (m0 + qr) * 528 + kb * 2);
            afr[kt][1] = *reinterpret_cast<const uint32_t*>(yb + (m0 + qr + 8) * 528 + kb * 2);
            afr[kt][2] = *reinterpret_cast<const uint32_t*>(yb + (m0 + qr) * 528 + (kb + 8) * 2);
            afr[kt][3] = *reinterpret_cast<const uint32_t*>(yb + (m0 + qr + 8) * 528 + (kb + 8) * 2);
        }
    }

    const char* wab = smem + K3_WA;
    const float2* bw = reinterpret_cast<const float2*>(smem + K3_BW);
    float s0 = 0.f, s1 = 0.f;

    #pragma unroll 2
    for (int j = 0; j < 32; j++) {
        float acc[4] = {0.f, 0.f, 0.f, 0.f};
        int nr = j * 8 + qr;
        #pragma unroll
        for (int kt = 0; kt < 16; kt++) {
            int kb = q4 * 2 + kt * 16;
            uint32_t b0 = *reinterpret_cast<const uint32_t*>(wab + nr * 528 + kb * 2);
            uint32_t b1 = *reinterpret_cast<const uint32_t*>(wab + nr * 528 + (kb + 8) * 2);
            mma16816(acc, afr[kt], b0, b1, acc);
        }
        int n0 = j * 8 + q4 * 2;
        float2 pp0 = bw[n0], pp1 = bw[n0 + 1];
        s0 += tanha(acc[0] + pp0.x) * pp0.y + tanha(acc[1] + pp1.x) * pp1.y;
        s1 += tanha(acc[2] + pp0.x) * pp0.y + tanha(acc[3] + pp1.x) * pp1.y;
    }
    s0 += __shfl_xor_sync(0xffffffffu, s0, 1);
    s0 += __shfl_xor_sync(0xffffffffu, s0, 2);
    s1 += __shfl_xor_sync(0xffffffffu, s1, 1);
    s1 += __shfl_xor_sync(0xffffffffu, s1, 2);
    if (q4 == 0) {
        g_scores[b][t0 + m0 + qr]     = s0;
        g_scores[b][t0 + m0 + qr + 8] = s1;
    }
}

// ---------------- K4: softmax over T + weighted sum ----------------
__global__ void __launch_bounds__(256) k4_soft(float* __restrict__ out)
{
    __shared__ float wb[TT];
    __shared__ float red[256];
    const int b = blockIdx.x, tid = threadIdx.x;

    float m = -1e30f;
    #pragma unroll
    for (int r = 0; r < 8; r++) m = fmaxf(m, g_scores[b][r * 256 + tid]);
    red[tid] = m; __syncthreads();
    for (int off = 128; off > 0; off >>= 1) {
        if (tid < off) red[tid] = fmaxf(red[tid], red[tid + off]);
        __syncthreads();
    }
    const float mx = red[0];
    __syncthreads();

    float ls = 0.f;
    #pragma unroll
    for (int r = 0; r < 8; r++) {
        int t = r * 256 + tid;
        float e = fast_ex2((g_scores[b][t] - mx) * LOG2E);
        wb[t] = e; ls += e;
    }
    red[tid] = ls; __syncthreads();
    for (int off = 128; off > 0; off >>= 1) {
        if (tid < off) red[tid] += red[tid + off];
        __syncthreads();
    }
    const float rz = __frcp_rn(red[0]);

    float acc = 0.f;
    const __half* yp = &g_y[b][0][tid];
    for (int t = 0; t < TT; t += 8) {
        #pragma unroll
        for (int u = 0; u < 8; u++)
            acc += wb[t + u] * __half2float(__ldg(yp + (size_t)(t + u) * H2));
    }
    out[b * H2 + tid] = acc * rz;
}

// ---------------- launch ----------------
extern "C" void kernel_launch(void* const* d_in, const int* in_sizes, int n_in,
                              void* d_out, int out_size)
{
    const float* x     = (const float*)d_in[0];
    const float* Wih_f = (const float*)d_in[1];
    const float* Whh_f = (const float*)d_in[2];
    const float* bih_f = (const float*)d_in[3];
    const float* bhh_f = (const float*)d_in[4];
    const float* Wih_b = (const float*)d_in[5];
    const float* Whh_b = (const float*)d_in[6];
    const float* bih_b = (const float*)d_in[7];
    const float* bhh_b = (const float*)d_in[8];
    const float* Wa    = (const float*)d_in[9];
    const float* ba    = (const float*)d_in[10];
    const float* Wu    = (const float*)d_in[11];
    float* out = (float*)d_out;

    cudaFuncSetAttribute(k1_mma, cudaFuncAttributeMaxDynamicSharedMemorySize, K1_TOT);
    cudaFuncSetAttribute(k3_mma, cudaFuncAttributeMaxDynamicSharedMemorySize, K3_TOT);

    p_wa<<<256, 256>>>(Wa);
    p_w1<<<256, 256>>>(Wih_f, Wih_b, bih_f, bhh_f, bih_b, bhh_b);
    k1_mma<<<dim3(TT / 128, BB), 256, K1_TOT>>>(x);
    k2_lstm<<<dim3(BB, 2), 256>>>(Whh_f, Whh_b);
    k3_mma<<<dim3(TT / 128, BB), 256, K3_TOT>>>(ba, Wu);
    k4_soft<<<BB, 256>>>(out);
}